// round 1
// baseline (speedup 1.0000x reference)
#include <cuda_runtime.h>
#include <math.h>

#define B_ 32
#define NF_ 16
#define N_ 192
#define D_ 256
#define S_ 21
#define BS_ (B_ * S_)   /* 672  */
#define BN_ (B_ * N_)   /* 6144 */

/* ------------------------------------------------------------------ */
/* scratch (device globals; no allocation anywhere)                    */
/* ------------------------------------------------------------------ */
__device__ float g_xln[BN_ * D_];
__device__ float g_k[BN_ * D_];
__device__ float g_v[BN_ * D_];
__device__ float g_slots[BS_ * D_];
__device__ float g_slots_ln[BS_ * D_];
__device__ float g_q[BS_ * D_];
__device__ float g_attn[B_ * S_ * N_];
__device__ float g_upd[BS_ * D_];
__device__ float g_gi[BS_ * 3 * D_];
__device__ float g_gh[BS_ * 3 * D_];
__device__ float g_h[BS_ * D_];
__device__ float g_hln[BS_ * D_];
__device__ float g_hidden[BS_ * D_];

/* ------------------------------------------------------------------ */
/* LayerNorm helpers (block per row, 256 threads, 1 elem/thread)       */
/* ------------------------------------------------------------------ */
__device__ __forceinline__ void ln_row_body(const float* __restrict__ src,
                                            float* __restrict__ dst,
                                            const float* __restrict__ gamma,
                                            const float* __restrict__ beta) {
    int d = threadIdx.x;
    float x = src[d];
    __shared__ float red[16];
    float s = x, q = x * x;
#pragma unroll
    for (int o = 16; o; o >>= 1) {
        s += __shfl_xor_sync(0xffffffffu, s, o);
        q += __shfl_xor_sync(0xffffffffu, q, o);
    }
    int w = threadIdx.x >> 5;
    if ((threadIdx.x & 31) == 0) { red[w] = s; red[8 + w] = q; }
    __syncthreads();
    if (threadIdx.x == 0) {
        float ts = 0.f, tq = 0.f;
#pragma unroll
        for (int i = 0; i < 8; i++) { ts += red[i]; tq += red[8 + i]; }
        red[0] = ts; red[8] = tq;
    }
    __syncthreads();
    float m = red[0] * (1.f / 256.f);
    float var = red[8] * (1.f / 256.f) - m * m;
    float rstd = rsqrtf(var + 1e-5f);
    dst[d] = (x - m) * rstd * gamma[d] + beta[d];
}

__global__ __launch_bounds__(256) void ln_gather_in(const float* __restrict__ inputs,
                                                    int f,
                                                    const float* __restrict__ gamma,
                                                    const float* __restrict__ beta) {
    int r = blockIdx.x;               /* 0..6143 */
    int b = r / N_;
    int hw = r % N_;
    const float* src = inputs + (((size_t)b * NF_ + f) * N_ + hw) * D_;
    ln_row_body(src, g_xln + (size_t)r * D_, gamma, beta);
}

__global__ __launch_bounds__(256) void ln_slots_k(const float* __restrict__ gamma,
                                                  const float* __restrict__ beta) {
    int r = blockIdx.x;
    ln_row_body(g_slots + (size_t)r * D_, g_slots_ln + (size_t)r * D_, gamma, beta);
}

__global__ __launch_bounds__(256) void ln_h_k(const float* __restrict__ gamma,
                                              const float* __restrict__ beta) {
    int r = blockIdx.x;
    ln_row_body(g_h + (size_t)r * D_, g_hln + (size_t)r * D_, gamma, beta);
}

/* ------------------------------------------------------------------ */
/* init slots: slots = mu + sigma * noise                              */
/* ------------------------------------------------------------------ */
__global__ __launch_bounds__(256) void init_slots(const float* __restrict__ noise,
                                                  const float* __restrict__ mu,
                                                  const float* __restrict__ sigma) {
    int row = blockIdx.x;
    int d = threadIdx.x;
    int i = row * D_ + d;
    g_slots[i] = mu[d] + sigma[d] * noise[i];
}

/* ------------------------------------------------------------------ */
/* tiled fp32 GEMM:  C[M,N] = A[M,K] @ W[N,K]^T + bias (+relu/+res)    */
/* CASE 0: K/V   (A=g_xln,   z=0 -> g_k, z=1 -> g_v)   M=6144 N=256    */
/* CASE 1: q     (A=g_slots_ln -> g_q)                  M=672  N=256    */
/* CASE 2: gi/gh (z=0: g_upd->g_gi, z=1: g_slots->g_gh) M=672  N=768    */
/* CASE 3: W1    (A=g_hln -> g_hidden, relu)            M=672  N=256    */
/* CASE 4: W2    (A=g_hidden -> g_slots, +g_h residual) M=672  N=256    */
/* ------------------------------------------------------------------ */
template <int CASE>
__global__ __launch_bounds__(256) void gemm_t(const float* __restrict__ B0,
                                              const float* __restrict__ B1,
                                              const float* __restrict__ bias0,
                                              const float* __restrict__ bias1) {
    constexpr int M = (CASE == 0) ? BN_ : BS_;
    constexpr int N = (CASE == 2) ? 3 * D_ : D_;
    constexpr int K = D_;

    const float* A;
    float* C;
    const float* res = nullptr;
    if (CASE == 0)      { A = g_xln;      C = blockIdx.z ? g_v  : g_k;  }
    else if (CASE == 1) { A = g_slots_ln; C = g_q; }
    else if (CASE == 2) { A = blockIdx.z ? g_slots : g_upd;
                          C = blockIdx.z ? g_gh    : g_gi; }
    else if (CASE == 3) { A = g_hln;      C = g_hidden; }
    else                { A = g_hidden;   C = g_slots; res = g_h; }
    const float* Bw   = blockIdx.z ? B1 : B0;
    const float* bias = blockIdx.z ? bias1 : bias0;

    __shared__ float As[16][64 + 4];
    __shared__ float Bs[16][64 + 4];

    int tid = threadIdx.x;
    int tx = tid & 15, ty = tid >> 4;
    int m0 = blockIdx.y * 64, n0 = blockIdx.x * 64;
    int lrow = tid >> 2;
    int lcol = (tid & 3) << 2;

    float acc[4][4] = {};

    for (int k0 = 0; k0 < K; k0 += 16) {
        float4 av = make_float4(0.f, 0.f, 0.f, 0.f);
        int gm = m0 + lrow;
        if ((M % 64 == 0) || gm < M)
            av = *(const float4*)(A + (size_t)gm * K + k0 + lcol);
        As[lcol + 0][lrow] = av.x;
        As[lcol + 1][lrow] = av.y;
        As[lcol + 2][lrow] = av.z;
        As[lcol + 3][lrow] = av.w;

        float4 bv = *(const float4*)(Bw + (size_t)(n0 + lrow) * K + k0 + lcol);
        Bs[lcol + 0][lrow] = bv.x;
        Bs[lcol + 1][lrow] = bv.y;
        Bs[lcol + 2][lrow] = bv.z;
        Bs[lcol + 3][lrow] = bv.w;
        __syncthreads();

#pragma unroll
        for (int kk = 0; kk < 16; kk++) {
            float4 a = *(const float4*)&As[kk][ty << 2];
            float4 b = *(const float4*)&Bs[kk][tx << 2];
            float ar[4] = {a.x, a.y, a.z, a.w};
            float br[4] = {b.x, b.y, b.z, b.w};
#pragma unroll
            for (int i = 0; i < 4; i++)
#pragma unroll
                for (int j = 0; j < 4; j++)
                    acc[i][j] += ar[i] * br[j];
        }
        __syncthreads();
    }

#pragma unroll
    for (int i = 0; i < 4; i++) {
        int gm = m0 + (ty << 2) + i;
        if ((M % 64 != 0) && gm >= M) continue;
        int gn = n0 + (tx << 2);
        float4 c = make_float4(acc[i][0], acc[i][1], acc[i][2], acc[i][3]);
        c.x += bias[gn + 0];
        c.y += bias[gn + 1];
        c.z += bias[gn + 2];
        c.w += bias[gn + 3];
        if (CASE == 3) {
            c.x = fmaxf(c.x, 0.f); c.y = fmaxf(c.y, 0.f);
            c.z = fmaxf(c.z, 0.f); c.w = fmaxf(c.w, 0.f);
        }
        if (CASE == 4) {
            const float* rp = res + (size_t)gm * N + gn;
            c.x += rp[0]; c.y += rp[1]; c.z += rp[2]; c.w += rp[3];
        }
        *(float4*)(C + (size_t)gm * N + gn) = c;
    }
}

/* ------------------------------------------------------------------ */
/* dots + softmax over slot axis (+eps); warp per pixel n              */
/* grid (24, 32), 256 threads (8 warps)                                */
/* ------------------------------------------------------------------ */
__global__ __launch_bounds__(256) void dots_softmax(float* __restrict__ attn_out,
                                                    int f) {
    int b = blockIdx.y;
    __shared__ float qs[S_ * D_];
    for (int i = threadIdx.x; i < S_ * D_; i += 256)
        qs[i] = g_q[(size_t)b * S_ * D_ + i];
    __syncthreads();

    int warp = threadIdx.x >> 5;
    int lane = threadIdx.x & 31;
    int n = blockIdx.x * 8 + warp;

    const float* krow = g_k + ((size_t)b * N_ + n) * D_;
    float kr[8];
#pragma unroll
    for (int i = 0; i < 8; i++) kr[i] = krow[i * 32 + lane];

    float dv[S_];
#pragma unroll
    for (int s = 0; s < S_; s++) {
        float p = 0.f;
#pragma unroll
        for (int i = 0; i < 8; i++) p += kr[i] * qs[s * D_ + i * 32 + lane];
#pragma unroll
        for (int o = 16; o; o >>= 1) p += __shfl_xor_sync(0xffffffffu, p, o);
        dv[s] = p * 0.0625f;  /* scale = 1/sqrt(256) */
    }
    float mx = -1e30f;
#pragma unroll
    for (int s = 0; s < S_; s++) mx = fmaxf(mx, dv[s]);
    float sum = 0.f;
#pragma unroll
    for (int s = 0; s < S_; s++) { dv[s] = expf(dv[s] - mx); sum += dv[s]; }
    float inv = 1.f / sum;
#pragma unroll
    for (int s = 0; s < S_; s++) {
        float a = dv[s] * inv + 1e-8f;
        if (lane == 0) {
            g_attn[((size_t)b * S_ + s) * N_ + n] = a;
            if (attn_out)
                attn_out[(((size_t)b * NF_ + f) * S_ + s) * N_ + n] = a;
        }
    }
}

/* ------------------------------------------------------------------ */
/* updates = (attn_ori @ v) / rowsum(attn_ori); grid (4, 32)           */
/* ------------------------------------------------------------------ */
__global__ __launch_bounds__(256) void updates_k() {
    int b = blockIdx.y;
    int d = blockIdx.x * 64 + (threadIdx.x & 63);
    int ty = threadIdx.x >> 6;  /* 0..3 */

    __shared__ float at[S_ * N_];
    __shared__ float inv[S_];
    for (int i = threadIdx.x; i < S_ * N_; i += 256)
        at[i] = g_attn[(size_t)b * S_ * N_ + i];
    __syncthreads();
    if (threadIdx.x < S_) {
        float s = 0.f;
        for (int j = 0; j < N_; j++) s += at[threadIdx.x * N_ + j];
        inv[threadIdx.x] = 1.f / s;
    }
    __syncthreads();

    float acc[6] = {0.f, 0.f, 0.f, 0.f, 0.f, 0.f};
    const float* vb = g_v + (size_t)b * N_ * D_;
    for (int j = 0; j < N_; j++) {
        float vj = vb[(size_t)j * D_ + d];
#pragma unroll
        for (int u = 0; u < 6; u++) {
            int s = ty + u * 4;
            if (s < S_) acc[u] += at[s * N_ + j] * vj;
        }
    }
#pragma unroll
    for (int u = 0; u < 6; u++) {
        int s = ty + u * 4;
        if (s < S_)
            g_upd[((size_t)b * S_ + s) * D_ + d] = acc[u] * inv[s];
    }
}

/* ------------------------------------------------------------------ */
/* GRU pointwise: h = (1-z)*n + z*slots                                */
/* ------------------------------------------------------------------ */
__device__ __forceinline__ float sigm(float x) { return 1.f / (1.f + expf(-x)); }

__global__ __launch_bounds__(256) void gru_pw() {
    int row = blockIdx.x;
    int d = threadIdx.x;
    const float* gi = g_gi + (size_t)row * 3 * D_;
    const float* gh = g_gh + (size_t)row * 3 * D_;
    float r = sigm(gi[d] + gh[d]);
    float z = sigm(gi[D_ + d] + gh[D_ + d]);
    float n = tanhf(gi[2 * D_ + d] + r * gh[2 * D_ + d]);
    g_h[(size_t)row * D_ + d] = (1.f - z) * n + z * g_slots[(size_t)row * D_ + d];
}

/* ------------------------------------------------------------------ */
/* final: copy first 20 slots of each batch to output                  */
/* ------------------------------------------------------------------ */
__global__ __launch_bounds__(256) void final_copy(float* __restrict__ out) {
    int idx = blockIdx.x * 256 + threadIdx.x;  /* 0 .. 32*20*256-1 */
    int d = idx & 255;
    int s = (idx >> 8) % 20;
    int b = idx / (20 * 256);
    out[idx] = g_slots[((size_t)(b * S_) + s) * D_ + d];
}

/* ------------------------------------------------------------------ */
extern "C" void kernel_launch(void* const* d_in, const int* in_sizes, int n_in,
                              void* d_out, int out_size) {
    const float* inputs = (const float*)d_in[0];
    const float* noise  = (const float*)d_in[1];
    const float* mu     = (const float*)d_in[2];
    const float* sigma  = (const float*)d_in[3];
    const float* Wq = (const float*)d_in[4];  const float* bq = (const float*)d_in[5];
    const float* Wk = (const float*)d_in[6];  const float* bk = (const float*)d_in[7];
    const float* Wv = (const float*)d_in[8];  const float* bv = (const float*)d_in[9];
    const float* W1 = (const float*)d_in[10]; const float* b1 = (const float*)d_in[11];
    const float* W2 = (const float*)d_in[12]; const float* b2 = (const float*)d_in[13];
    const float* Wih = (const float*)d_in[14]; const float* bih = (const float*)d_in[15];
    const float* Whh = (const float*)d_in[16]; const float* bhh = (const float*)d_in[17];
    const float* gin = (const float*)d_in[18]; const float* bein = (const float*)d_in[19];
    const float* gsl = (const float*)d_in[20]; const float* besl = (const float*)d_in[21];
    const float* gff = (const float*)d_in[22]; const float* beff = (const float*)d_in[23];

    float* out = (float*)d_out;
    float* out_slots = out;
    float* out_attn = out + (size_t)B_ * 20 * D_;

    init_slots<<<BS_, 256>>>(noise, mu, sigma);

    for (int f = 0; f < NF_; f++) {
        ln_gather_in<<<BN_, 256>>>(inputs, f, gin, bein);
        gemm_t<0><<<dim3(4, 96, 2), 256>>>(Wk, Wv, bk, bv);

        for (int it = 0; it < 3; it++) {
            ln_slots_k<<<BS_, 256>>>(gsl, besl);
            gemm_t<1><<<dim3(4, 11, 1), 256>>>(Wq, Wq, bq, bq);
            dots_softmax<<<dim3(24, B_), 256>>>((it == 2) ? out_attn : nullptr, f);
            updates_k<<<dim3(4, B_), 256>>>();
            gemm_t<2><<<dim3(12, 11, 2), 256>>>(Wih, Whh, bih, bhh);
            gru_pw<<<BS_, 256>>>();
            ln_h_k<<<BS_, 256>>>(gff, beff);
            gemm_t<3><<<dim3(4, 11, 1), 256>>>(W1, W1, b1, b1);
            gemm_t<4><<<dim3(4, 11, 1), 256>>>(W2, W2, b2, b2);
        }
    }

    final_copy<<<(B_ * 20 * D_) / 256, 256>>>(out_slots);
}